// round 14
// baseline (speedup 1.0000x reference)
#include <cuda_runtime.h>
#include <cstdint>

#define Bc   16
#define NFc  16
#define Nc   1024
#define Dc   128
#define Sc   8
#define Hc   128
#define BSc  (Bc*Sc)
#define CHTOK 128             // tokens per rank-block
#define SCALEc 0.08838834764831845f
#define EPSc   1e-8f

// ---------------- folded weights (prep output) ----------------
__device__ float g_WcT[Dc*3*Dc];      // (Wih @ Wv)^T : [e][j]
__device__ float g_bc[3*Dc];          // Wih @ bv
__device__ float g_WhhT[Dc*3*Dc];     // Whh^T [e][j]
__device__ float g_W1T[Dc*Hc];
__device__ float g_W2T[Hc*Dc];
__device__ float g_MT[Dc*Dc];         // MT[e][d] = (Wk^T Wq)[d][e]
__device__ float g_qtb[Dc];           // Wk^T bq
__device__ float g_qbv[Dc];           // Wq^T bk
__device__ float g_qbb[1];            // bq . bk

// ---------------- smem layout (floats) ----------------
#define XST 132
#define O_XS   0                      // 128*132 = 16896  (stepB x; stepC scratch)
#define O_QTS  16896                  // 8*132
#define O_AS   17952                  // 8*132
#define O_YAS  19008                  // 8*128 (peer-read)
#define O_RS8  20032                  // 8     (peer-read)
#define O_QBS  20040                  // 8
#define O_HSV  20048                  // 128 (persistent slot value)
#define O_GI   20176                  // 384
#define O_GH   20560                  // 384
#define O_PART 20944                  // 512
#define O_RED  21456                  // 16
#define O_MISC 21472                  // 8
#define SM_FLOATS 21480
#define SMEM_BYTES (SM_FLOATS*4)

// ---------------- asm helpers ----------------
__device__ __forceinline__ float sigmoidf_(float x) { return 1.0f / (1.0f + expf(-x)); }

__device__ __forceinline__ uint32_t smem_u32(const void* p) {
    uint32_t a;
    asm("{ .reg .u64 t; cvta.to.shared.u64 t, %1; cvt.u32.u64 %0, t; }" : "=r"(a) : "l"(p));
    return a;
}
__device__ __forceinline__ uint32_t cluster_rank() {
    uint32_t r; asm("mov.u32 %0, %%cluster_ctarank;" : "=r"(r)); return r;
}
__device__ __forceinline__ float dsmem_ld(uint32_t addr, uint32_t rank) {
    uint32_t ra;
    asm("mapa.shared::cluster.u32 %0, %1, %2;" : "=r"(ra) : "r"(addr), "r"(rank));
    float v;
    asm volatile("ld.shared::cluster.f32 %0, [%1];" : "=f"(v) : "r"(ra));
    return v;
}
__device__ __forceinline__ void dsmem_st(uint32_t addr, uint32_t rank, float v) {
    uint32_t ra;
    asm("mapa.shared::cluster.u32 %0, %1, %2;" : "=r"(ra) : "r"(addr), "r"(rank));
    asm volatile("st.shared::cluster.f32 [%0], %1;" :: "r"(ra), "f"(v));
}
__device__ __forceinline__ void cluster_sync() {
    asm volatile("barrier.cluster.arrive.aligned;" ::: "memory");
    asm volatile("barrier.cluster.wait.aligned;" ::: "memory");
}

// block sum over 512 threads (inactive lanes pass 0)
__device__ __forceinline__ float bsum512(float v, float* red) {
    #pragma unroll
    for (int o = 16; o; o >>= 1) v += __shfl_xor_sync(0xffffffffu, v, o);
    int t = threadIdx.x;
    if ((t & 31) == 0) red[t >> 5] = v;
    __syncthreads();
    float r = 0.0f;
    #pragma unroll
    for (int i = 0; i < 16; i++) r += red[i];
    __syncthreads();
    return r;
}

// ---------------- prep: transposes, folded matrices, bias vectors -------
__global__ void prep_kernel(const float* __restrict__ Wq, const float* __restrict__ bq,
                            const float* __restrict__ Wk, const float* __restrict__ bk,
                            const float* __restrict__ W1, const float* __restrict__ W2,
                            const float* __restrict__ Wih, const float* __restrict__ Whh,
                            const float* __restrict__ Wv, const float* __restrict__ bv) {
    int blk = blockIdx.x;
    int t = threadIdx.x;
    if (blk < 192) {
        int idx = blk * 256 + t;
        int j = idx >> 7, d = idx & 127;
        g_WhhT[d * 384 + j] = Whh[idx];
        if (idx < Dc * Dc) {
            int r = idx >> 7, c = idx & 127;
            g_W1T[c * Dc + r] = W1[idx];
            g_W2T[c * Dc + r] = W2[idx];
        }
    } else if (blk == 192) {
        if (t < 128) {
            float aq = 0.0f, ab = 0.0f;
            for (int j = 0; j < 128; j++) {
                aq += Wq[j * 128 + t] * bk[j];
                ab += Wk[j * 128 + t] * bq[j];
            }
            g_qbv[t] = aq;
            g_qtb[t] = ab;
            if (t == 0) {
                float s = 0.0f;
                for (int j = 0; j < 128; j++) s += bq[j] * bk[j];
                g_qbb[0] = s;
            }
        }
        for (int j = t; j < 384; j += 256) {
            float s = 0.0f;
            for (int d = 0; d < 128; d++) s += Wih[j * 128 + d] * bv[d];
            g_bc[j] = s;
        }
    } else if (blk < 577) {
        __shared__ float row[128];
        int j = blk - 193;
        if (t < 128) row[t] = Wih[j * 128 + t];
        __syncthreads();
        if (t < 128) {
            float s = 0.0f;
            #pragma unroll 8
            for (int d = 0; d < 128; d++) s += row[d] * Wv[d * 128 + t];
            g_WcT[t * 384 + j] = s;
        }
    } else {
        int e = blk - 577;
        if (t < 128) {
            float s = 0.0f;
            #pragma unroll 8
            for (int j = 0; j < 128; j++) s += Wk[j * 128 + t] * Wq[j * 128 + e];
            g_MT[e * 128 + t] = s;
        }
    }
}

// ---------------- main: 16 clusters x 8 blocks, 512 threads -------------
__global__ void __launch_bounds__(512, 1) __cluster_dims__(8, 1, 1)
main_kernel(const float* __restrict__ x, const float* __restrict__ slots_init,
            float* __restrict__ out_slots, float* __restrict__ out_attn,
            const float* __restrict__ bih, const float* __restrict__ bhh,
            const float* __restrict__ g_ff, const float* __restrict__ be_ff,
            const float* __restrict__ b1, const float* __restrict__ b2,
            const float* __restrict__ g_sl, const float* __restrict__ be_sl,
            const float* __restrict__ g_in, const float* __restrict__ be_in) {
    extern __shared__ float sm[];
    const int t = threadIdx.x;
    const int lane = t & 31, w = t >> 5;
    const uint32_t r = cluster_rank();        // chunk AND slot index
    const int b = blockIdx.x >> 3;            // batch

    float* xs  = sm + O_XS;
    float* qts = sm + O_QTS;
    float* as  = sm + O_AS;
    float* yas = sm + O_YAS;
    float* rs8 = sm + O_RS8;
    float* qbs = sm + O_QBS;
    float* hsv = sm + O_HSV;
    float* gi  = sm + O_GI;
    float* gh  = sm + O_GH;
    float* part = sm + O_PART;
    float* red  = sm + O_RED;
    // stepC scratch aliases inside xs region
    float* yn  = xs;            // 128
    float* ffs = xs + 128;      // 128
    float* hid = xs + 256;      // 128
    float* ln2 = xs + 384;      // 128
    float* hgs = xs + 512;      // 128

    const uint32_t smb = smem_u32(sm);

    // ======== init: slot r value + first qt/qb, multicast to peers ========
    if (t < 128) hsv[t] = slots_init[r * Dc + t];
    __syncthreads();
    {
        float v = (t < 128) ? hsv[t] : 0.0f;
        float m = bsum512(v, red) * (1.0f / 128.0f);
        float dx = (t < 128) ? (hsv[t] - m) : 0.0f;
        float var = bsum512(dx * dx, red) * (1.0f / 128.0f);
        if (t < 128) ln2[t] = dx * rsqrtf(var + 1e-5f) * g_sl[t] + be_sl[t];
        __syncthreads();
        // qt = MT ln2 + qtb (split-K 4)
        {
            int col = t & 127, h = t >> 7;
            float acc = 0.0f;
            #pragma unroll 8
            for (int i = 0; i < 32; i++) {
                int e = h * 32 + i;
                acc += g_MT[e * 128 + col] * ln2[e];
            }
            part[h * 128 + col] = acc;
        }
        float qv = (t < 128) ? (g_qbv[t] * ln2[t]) : 0.0f;
        float qb = bsum512(qv, red) + g_qbb[0];  // bsum512 has syncthreads inside
        if (t < 128) {
            float qtv = part[t] + part[128 + t] + part[256 + t] + part[384 + t] + g_qtb[t];
            uint32_t addr = smb + (uint32_t)(O_QTS + (int)r * XST + t) * 4u;
            #pragma unroll
            for (int p = 0; p < 8; p++) dsmem_st(addr, p, qtv);
        }
        if (t == 0) {
            uint32_t addr = smb + (uint32_t)(O_QBS + (int)r) * 4u;
            #pragma unroll
            for (int p = 0; p < 8; p++) dsmem_st(addr, p, qb);
        }
    }
    cluster_sync();

    float4 gg = ((const float4*)g_in)[lane];
    float4 bb = ((const float4*)be_in)[lane];

    for (int step = 0; step <= NFc; step++) {
        const int f = (step == 0) ? 0 : step - 1;
        const int emit = (step > 0) ? 1 : 0;
        const int bf = b * NFc + f;

        // ================= stepB: 128 tokens per block =================
        {
            const float* xg = x + ((size_t)bf * Nc + (size_t)r * CHTOK) * Dc;
            // LN: 16 warps x 8 rows
            #pragma unroll
            for (int rr = w; rr < CHTOK; rr += 16) {
                float4 v = ((const float4*)(xg + rr * Dc))[lane];
                float s = v.x + v.y + v.z + v.w;
                #pragma unroll
                for (int o = 16; o; o >>= 1) s += __shfl_xor_sync(0xffffffffu, s, o);
                float m = s * (1.0f / 128.0f);
                float d0 = v.x - m, d1 = v.y - m, d2 = v.z - m, d3 = v.w - m;
                float ss = d0*d0 + d1*d1 + d2*d2 + d3*d3;
                #pragma unroll
                for (int o = 16; o; o >>= 1) ss += __shfl_xor_sync(0xffffffffu, ss, o);
                float inv = rsqrtf(ss * (1.0f / 128.0f) + 1e-5f);
                float* xr = xs + rr * XST + lane * 4;
                xr[0] = d0 * inv * gg.x + bb.x;
                xr[1] = d1 * inv * gg.y + bb.y;
                xr[2] = d2 * inv * gg.z + bb.z;
                xr[3] = d3 * inv * gg.w + bb.w;
            }
            __syncthreads();

            // dots: thread -> slot s = t&7, tokens tt0 = t>>3 and tt0+64
            const int tt0 = t >> 3;
            const int s = t & 7;
            float dot0 = 0.0f, dot1 = 0.0f;
            const float* qrow = qts + s * XST;
            const float* xrow0 = xs + tt0 * XST;
            const float* xrow1 = xrow0 + 64 * XST;
            #pragma unroll 8
            for (int j = 0; j < 32; j++) {
                float4 q4 = *(const float4*)(qrow + j * 4);
                float4 x0 = *(const float4*)(xrow0 + j * 4);
                float4 x1 = *(const float4*)(xrow1 + j * 4);
                dot0 += q4.x*x0.x + q4.y*x0.y + q4.z*x0.z + q4.w*x0.w;
                dot1 += q4.x*x1.x + q4.y*x1.y + q4.z*x1.z + q4.w*x1.w;
            }
            float qbv2 = qbs[s];
            dot0 = (dot0 + qbv2) * SCALEc;
            dot1 = (dot1 + qbv2) * SCALEc;
            float mx0 = dot0, mx1 = dot1;
            #pragma unroll
            for (int o = 4; o; o >>= 1) {
                mx0 = fmaxf(mx0, __shfl_xor_sync(0xffffffffu, mx0, o));
                mx1 = fmaxf(mx1, __shfl_xor_sync(0xffffffffu, mx1, o));
            }
            float e0 = expf(dot0 - mx0), e1 = expf(dot1 - mx1);
            float s0 = e0, s1 = e1;
            #pragma unroll
            for (int o = 4; o; o >>= 1) {
                s0 += __shfl_xor_sync(0xffffffffu, s0, o);
                s1 += __shfl_xor_sync(0xffffffffu, s1, o);
            }
            as[s * XST + tt0]      = e0 / s0 + EPSc;
            as[s * XST + tt0 + 64] = e1 / s1 + EPSc;
            __syncthreads();

            if (emit) {
                #pragma unroll
                for (int i = 0; i < 2; i++) {
                    int idx = t + i * 512;
                    int s3 = idx >> 7, n3 = idx & 127;
                    out_attn[(size_t)bf * Sc * Nc + (size_t)s3 * Nc + (size_t)r * CHTOK + n3]
                        = as[s3 * XST + n3];
                }
            }

            // warps 0-7: ya for slot w; warps 8-15: rowsum for slot w-8
            if (w < 8) {
                float4 up = make_float4(0.f, 0.f, 0.f, 0.f);
                const float* arow = as + w * XST;
                #pragma unroll 8
                for (int n = 0; n < CHTOK; n++) {
                    float a2 = arow[n];
                    float4 v4 = *(const float4*)(xs + n * XST + lane * 4);
                    up.x += a2 * v4.x; up.y += a2 * v4.y;
                    up.z += a2 * v4.z; up.w += a2 * v4.w;
                }
                *(float4*)(yas + w * 128 + lane * 4) = up;
            } else {
                int s2 = w - 8;
                const float* arow = as + s2 * XST;
                float rv = arow[lane] + arow[lane + 32] + arow[lane + 64] + arow[lane + 96];
                #pragma unroll
                for (int o = 16; o; o >>= 1) rv += __shfl_xor_sync(0xffffffffu, rv, o);
                if (lane == 0) rs8[s2] = rv;
            }
        }
        cluster_sync();   // publish yas/rs8; protects qts rewrite below

        // ================= stepC: slot r per block =================
        {
            // gather ya partials for slot r from all peers
            if (t < 128) {
                uint32_t addr = smb + (uint32_t)(O_YAS + (int)r * 128 + t) * 4u;
                float acc = 0.0f;
                #pragma unroll
                for (int p = 0; p < 8; p++) acc += dsmem_ld(addr, p);
                yn[t] = acc;
            }
            if (t >= 128 && t < 136) {
                uint32_t addr = smb + (uint32_t)(O_RS8 + (int)r) * 4u;
                red[t - 128] = dsmem_ld(addr, t - 128);
            }
            __syncthreads();
            if (t < 128) {
                float rsum = red[0] + red[1] + red[2] + red[3]
                           + red[4] + red[5] + red[6] + red[7];
                yn[t] /= rsum;
            }
            __syncthreads();

            // gates: gi[0..383] from yn; gh[0..383] from hsv
            {
                int c = t;
                if (c < 384) {
                    float acc = 0.0f;
                    #pragma unroll 16
                    for (int e = 0; e < 128; e++) acc += g_WcT[e * 384 + c] * yn[e];
                    gi[c] = acc;
                } else {
                    int j = c - 384;
                    float acc = 0.0f;
                    #pragma unroll 16
                    for (int e = 0; e < 128; e++) acc += g_WhhT[e * 384 + j] * hsv[e];
                    gh[j] = acc;
                }
                if (t < 256) {
                    int j = 128 + t;
                    float acc = 0.0f;
                    #pragma unroll 16
                    for (int e = 0; e < 128; e++) acc += g_WhhT[e * 384 + j] * hsv[e];
                    gh[j] = acc;
                }
            }
            __syncthreads();

            // GRU
            float hg = 0.0f;
            if (t < 128) {
                float gi_r = gi[t]       + g_bc[t]       + bih[t];
                float gh_r = gh[t]       + bhh[t];
                float gi_z = gi[128 + t] + g_bc[128 + t] + bih[128 + t];
                float gh_z = gh[128 + t] + bhh[128 + t];
                float gi_n = gi[256 + t] + g_bc[256 + t] + bih[256 + t];
                float gh_n = gh[256 + t] + bhh[256 + t];
                float rr2 = sigmoidf_(gi_r + gh_r);
                float z   = sigmoidf_(gi_z + gh_z);
                float nn  = tanhf(gi_n + rr2 * gh_n);
                hg = (1.0f - z) * nn + z * hsv[t];
                hgs[t] = hg;
            }
            {
                float v = (t < 128) ? hg : 0.0f;
                float m = bsum512(v, red) * (1.0f / 128.0f);
                float dx = (t < 128) ? (hg - m) : 0.0f;
                float var = bsum512(dx * dx, red) * (1.0f / 128.0f);
                if (t < 128) ffs[t] = dx * rsqrtf(var + 1e-5f) * g_ff[t] + be_ff[t];
            }
            __syncthreads();

            // FF1 split-K4
            {
                int col = t & 127, h = t >> 7;
                float acc = 0.0f;
                #pragma unroll 8
                for (int i = 0; i < 32; i++) {
                    int d = h * 32 + i;
                    acc += g_W1T[d * Dc + col] * ffs[d];
                }
                part[h * 128 + col] = acc;
            }
            __syncthreads();
            if (t < 128)
                hid[t] = fmaxf(part[t] + part[128 + t] + part[256 + t] + part[384 + t] + b1[t], 0.0f);
            __syncthreads();

            // FF2 split-K4
            {
                int col = t & 127, h = t >> 7;
                float acc = 0.0f;
                #pragma unroll 8
                for (int i = 0; i < 32; i++) {
                    int d = h * 32 + i;
                    acc += g_W2T[d * Dc + col] * hid[d];
                }
                part[h * 128 + col] = acc;
            }
            __syncthreads();
            float snew = 0.0f;
            if (t < 128) {
                snew = hgs[t] + part[t] + part[128 + t] + part[256 + t] + part[384 + t] + b2[t];
                hsv[t] = snew;
                if (emit)
                    out_slots[(((size_t)b * NFc + f) * Sc + r) * Dc + t] = snew;
            }

            // LN -> qb, qt; multicast
            {
                float v = (t < 128) ? snew : 0.0f;
                float m = bsum512(v, red) * (1.0f / 128.0f);
                float dx = (t < 128) ? (snew - m) : 0.0f;
                float var = bsum512(dx * dx, red) * (1.0f / 128.0f);
                if (t < 128) ln2[t] = dx * rsqrtf(var + 1e-5f) * g_sl[t] + be_sl[t];
            }
            __syncthreads();
            float qv = (t < 128) ? (g_qbv[t] * ln2[t]) : 0.0f;
            float qbnew = bsum512(qv, red) + g_qbb[0];
            {
                int col = t & 127, h = t >> 7;
                float acc = 0.0f;
                #pragma unroll 8
                for (int i = 0; i < 32; i++) {
                    int e = h * 32 + i;
                    acc += g_MT[e * 128 + col] * ln2[e];
                }
                part[h * 128 + col] = acc;
            }
            __syncthreads();
            if (t < 128) {
                float qtv = part[t] + part[128 + t] + part[256 + t] + part[384 + t] + g_qtb[t];
                uint32_t addr = smb + (uint32_t)(O_QTS + (int)r * XST + t) * 4u;
                #pragma unroll
                for (int p = 0; p < 8; p++) dsmem_st(addr, p, qtv);
            }
            if (t == 0) {
                uint32_t addr = smb + (uint32_t)(O_QBS + (int)r) * 4u;
                #pragma unroll
                for (int p = 0; p < 8; p++) dsmem_st(addr, p, qbnew);
            }
        }
        cluster_sync();   // publish qts/qbs for next stepB
    }
}

// ---------------- launch ----------------
extern "C" void kernel_launch(void* const* d_in, const int* in_sizes, int n_in,
                              void* d_out, int out_size) {
    const float* inputs     = (const float*)d_in[0];
    const float* slots_init = (const float*)d_in[1];
    const float* Wq  = (const float*)d_in[2];
    const float* bq  = (const float*)d_in[3];
    const float* Wk  = (const float*)d_in[4];
    const float* bk  = (const float*)d_in[5];
    const float* Wv  = (const float*)d_in[6];
    const float* bv  = (const float*)d_in[7];
    const float* W1  = (const float*)d_in[8];
    const float* b1  = (const float*)d_in[9];
    const float* W2  = (const float*)d_in[10];
    const float* b2  = (const float*)d_in[11];
    const float* Wih = (const float*)d_in[12];
    const float* Whh = (const float*)d_in[13];
    const float* bih = (const float*)d_in[14];
    const float* bhh = (const float*)d_in[15];
    const float* g_in  = (const float*)d_in[16];
    const float* be_in = (const float*)d_in[17];
    const float* g_sl  = (const float*)d_in[18];
    const float* be_sl = (const float*)d_in[19];
    const float* g_ff  = (const float*)d_in[20];
    const float* be_ff = (const float*)d_in[21];

    float* out = (float*)d_out;
    float* out_slots = out;                                 // [B,NF,S,D]
    float* out_attn  = out + (size_t)Bc * NFc * Sc * Dc;    // [B,NF,S,N]

    cudaFuncSetAttribute(main_kernel, cudaFuncAttributeMaxDynamicSharedMemorySize, SMEM_BYTES);

    prep_kernel<<<705, 256>>>(Wq, bq, Wk, bk, W1, W2, Wih, Whh, Wv, bv);
    main_kernel<<<BSc, 512, SMEM_BYTES>>>(inputs, slots_init, out_slots, out_attn,
                                          bih, bhh, g_ff, be_ff, b1, b2,
                                          g_sl, be_sl, g_in, be_in);
}

// round 15
// speedup vs baseline: 1.4934x; 1.4934x over previous
#include <cuda_runtime.h>
#include <cstdint>

#define Bc   16
#define NFc  16
#define Nc   1024
#define Dc   128
#define Sc   8
#define Hc   128
#define BSc  (Bc*Sc)          // 128
#define NCHUNK 32
#define CHTOK  32             // tokens per chunk
#define SCALEc 0.08838834764831845f
#define EPSc   1e-8f

// ---------------- device scratch ----------------
__device__ float g_qt[BSc*Dc];
__device__ float g_qb[BSc];
__device__ float g_slots[BSc*Dc];
__device__ float g_Yapart[NCHUNK*BSc*Dc];   // 2 MB
__device__ float g_rspart[NCHUNK*BSc];
__device__ float g_WcT[Dc*3*Dc];      // (Wih @ Wv)^T : [e][j]
__device__ float g_bc[3*Dc];          // Wih @ bv
__device__ float g_WhhT[Dc*3*Dc];
__device__ float g_W1T[Dc*Hc];
__device__ float g_W2T[Hc*Dc];
__device__ float g_MT[Dc*Dc];         // MT[e][d] = (Wk^T Wq)[d][e]
__device__ float g_qtb[Dc];           // Wk^T bq
__device__ float g_qbv[Dc];           // Wq^T bk
__device__ float g_qbb[1];            // bq . bk

// ---------------- helpers ----------------
__device__ __forceinline__ float sigmoidf_(float x) { return 1.0f / (1.0f + expf(-x)); }

__device__ __forceinline__ float bsum256(float v, float* red) {
    #pragma unroll
    for (int o = 16; o; o >>= 1) v += __shfl_xor_sync(0xffffffffu, v, o);
    int t = threadIdx.x;
    if ((t & 31) == 0) red[t >> 5] = v;
    __syncthreads();
    float r = red[0] + red[1] + red[2] + red[3] + red[4] + red[5] + red[6] + red[7];
    __syncthreads();
    return r;
}

__device__ __forceinline__ float rowsum2(float v, float red[2][4]) {
    int t = threadIdx.x;
    int lane = t & 31, wid = t >> 5;
    #pragma unroll
    for (int o = 16; o; o >>= 1) v += __shfl_xor_sync(0xffffffffu, v, o);
    if (t < 256 && lane == 0) red[wid >> 2][wid & 3] = v;
    __syncthreads();
    float s = 0.0f;
    if (t < 256) {
        int r = t >> 7;
        s = red[r][0] + red[r][1] + red[r][2] + red[r][3];
    }
    __syncthreads();
    return s;
}

// ---------------- prep: transposes, folded matrices, bias vectors -------
__global__ void prep_kernel(const float* __restrict__ Wq, const float* __restrict__ bq,
                            const float* __restrict__ Wk, const float* __restrict__ bk,
                            const float* __restrict__ W1, const float* __restrict__ W2,
                            const float* __restrict__ Wih, const float* __restrict__ Whh,
                            const float* __restrict__ Wv, const float* __restrict__ bv) {
    int blk = blockIdx.x;
    int t = threadIdx.x;
    if (blk < 192) {
        int idx = blk * 256 + t;
        int j = idx >> 7, d = idx & 127;
        g_WhhT[d * 384 + j] = Whh[idx];
        if (idx < Dc * Dc) {
            int r = idx >> 7, c = idx & 127;
            g_W1T[c * Dc + r] = W1[idx];
            g_W2T[c * Dc + r] = W2[idx];
        }
    } else if (blk == 192) {
        if (t < 128) {
            float aq = 0.0f, ab = 0.0f;
            for (int j = 0; j < 128; j++) {
                aq += Wq[j * 128 + t] * bk[j];
                ab += Wk[j * 128 + t] * bq[j];
            }
            g_qbv[t] = aq;
            g_qtb[t] = ab;
            if (t == 0) {
                float s = 0.0f;
                for (int j = 0; j < 128; j++) s += bq[j] * bk[j];
                g_qbb[0] = s;
            }
        }
        for (int j = t; j < 384; j += 256) {
            float s = 0.0f;
            for (int d = 0; d < 128; d++) s += Wih[j * 128 + d] * bv[d];
            g_bc[j] = s;
        }
    } else if (blk < 577) {
        __shared__ float row[128];
        int j = blk - 193;
        if (t < 128) row[t] = Wih[j * 128 + t];
        __syncthreads();
        if (t < 128) {
            float s = 0.0f;
            #pragma unroll 8
            for (int d = 0; d < 128; d++) s += row[d] * Wv[d * 128 + t];
            g_WcT[t * 384 + j] = s;
        }
    } else {
        int e = blk - 577;
        if (t < 128) {
            float s = 0.0f;
            #pragma unroll 8
            for (int j = 0; j < 128; j++) s += Wk[j * 128 + t] * Wq[j * 128 + e];
            g_MT[e * 128 + t] = s;
        }
    }
}

// ---------------- init: slots broadcast + first qt/qb -------------------
__global__ void init_kernel(const float* __restrict__ slots_init,
                            const float* __restrict__ g_sl, const float* __restrict__ be_sl) {
    __shared__ float lnv[Dc];
    __shared__ float part[2][Dc];
    __shared__ float red[8];
    const int t = threadIdx.x;
    const int bs = blockIdx.x;
    const int s = bs & 7;
    float v = 0.0f;
    if (t < 128) {
        v = slots_init[s * Dc + t];
        g_slots[bs * Dc + t] = v;
    }
    float m = bsum256(v, red) * (1.0f / 128.0f);
    float dx = (t < 128) ? (v - m) : 0.0f;
    float var = bsum256(dx * dx, red) * (1.0f / 128.0f);
    if (t < 128) lnv[t] = dx * rsqrtf(var + 1e-5f) * g_sl[t] + be_sl[t];
    __syncthreads();
    {
        int col = t & 127, h2 = t >> 7;
        float acc = 0.0f;
        #pragma unroll 8
        for (int i = 0; i < 64; i++) {
            int e = h2 * 64 + i;
            acc += g_MT[e * 128 + col] * lnv[e];
        }
        part[h2][col] = acc;
    }
    __syncthreads();
    if (t < 128) g_qt[bs * Dc + t] = part[0][t] + part[1][t] + g_qtb[t];
    float qv = (t < 128) ? (g_qbv[t] * lnv[t]) : 0.0f;
    float qb = bsum256(qv, red);
    if (t == 0) g_qb[bs] = qb + g_qbb[0];
}

// ---------------- stepB: LN(x), dots, softmax, ya/ra partials -----------
// grid (32 chunks of 32 tokens, 16 batches) = 512 blocks, 256 threads
#define XST 132
#define ASTB 33
__global__ void __launch_bounds__(256) stepB_kernel(
        const float* __restrict__ x, int f, int emit, float* __restrict__ out_attn,
        const float* __restrict__ g_in, const float* __restrict__ be_in) {
    __shared__ float xs[CHTOK * XST];
    __shared__ float qts[Sc * XST];
    __shared__ float as[Sc * ASTB];
    __shared__ float qbs[Sc];

    const int t = threadIdx.x;
    const int lane = t & 31, w = t >> 5;
    const int chunk = blockIdx.x;
    const int b = blockIdx.y;
    const int bf = b * NFc + f;
    const float* xg = x + ((size_t)bf * Nc + (size_t)chunk * CHTOK) * Dc;

    float4 gg = ((const float4*)g_in)[lane];
    float4 bb = ((const float4*)be_in)[lane];
    // LN: warp w handles rows w, w+8, w+16, w+24 — loads front-batched (MLP=4)
    float4 vv[4];
    #pragma unroll
    for (int i = 0; i < 4; i++)
        vv[i] = ((const float4*)(xg + (w + i * 8) * Dc))[lane];
    {
        int s0 = t >> 5, dq0 = (t & 31) * 4;
        *(float4*)(qts + s0 * XST + dq0) = *(const float4*)(g_qt + (b * Sc + s0) * Dc + dq0);
    }
    if (t < 8) qbs[t] = g_qb[b * Sc + t];
    #pragma unroll
    for (int i = 0; i < 4; i++) {
        int r = w + i * 8;
        float4 v = vv[i];
        float s = v.x + v.y + v.z + v.w;
        #pragma unroll
        for (int o = 16; o; o >>= 1) s += __shfl_xor_sync(0xffffffffu, s, o);
        float m = s * (1.0f / 128.0f);
        float d0 = v.x - m, d1 = v.y - m, d2 = v.z - m, d3 = v.w - m;
        float ss = d0*d0 + d1*d1 + d2*d2 + d3*d3;
        #pragma unroll
        for (int o = 16; o; o >>= 1) ss += __shfl_xor_sync(0xffffffffu, ss, o);
        float inv = rsqrtf(ss * (1.0f / 128.0f) + 1e-5f);
        float* xr = xs + r * XST + lane * 4;
        xr[0] = d0 * inv * gg.x + bb.x;
        xr[1] = d1 * inv * gg.y + bb.y;
        xr[2] = d2 * inv * gg.z + bb.z;
        xr[3] = d3 * inv * gg.w + bb.w;
    }
    __syncthreads();

    // dots: thread -> (token tt, slot s)
    const int tt = t >> 3;
    const int s = t & 7;
    float dot = 0.0f;
    const float* qrow = qts + s * XST;
    const float* xrow = xs + tt * XST;
    #pragma unroll 8
    for (int j = 0; j < 32; j++) {
        float4 q4 = *(const float4*)(qrow + j * 4);
        float4 x4 = *(const float4*)(xrow + j * 4);
        dot += q4.x*x4.x + q4.y*x4.y + q4.z*x4.z + q4.w*x4.w;
    }
    dot = (dot + qbs[s]) * SCALEc;
    float mx = dot;
    #pragma unroll
    for (int o = 4; o; o >>= 1) mx = fmaxf(mx, __shfl_xor_sync(0xffffffffu, mx, o));
    float e = expf(dot - mx);
    float es = e;
    #pragma unroll
    for (int o = 4; o; o >>= 1) es += __shfl_xor_sync(0xffffffffu, es, o);
    float a = e / es + EPSc;
    as[s * ASTB + tt] = a;
    __syncthreads();

    // coalesced attn emit (8 slots x 32 tokens)
    if (emit) {
        int s3 = t >> 5, n3 = t & 31;
        out_attn[(size_t)bf * Sc * Nc + (size_t)s3 * Nc + chunk * CHTOK + n3] = as[s3 * ASTB + n3];
    }

    // rowsum: warp w -> slot w
    {
        float rs = as[w * ASTB + lane];
        #pragma unroll
        for (int o = 16; o; o >>= 1) rs += __shfl_xor_sync(0xffffffffu, rs, o);
        if (lane == 0) g_rspart[chunk * BSc + b * Sc + w] = rs;
    }

    // ya partials: warp w -> slot w; lane owns d-quad
    {
        float4 up = make_float4(0.f, 0.f, 0.f, 0.f);
        const float* arow = as + w * ASTB;
        #pragma unroll 8
        for (int n = 0; n < CHTOK; n++) {
            float a2 = arow[n];
            float4 v4 = *(const float4*)(xs + n * XST + lane * 4);
            up.x += a2 * v4.x; up.y += a2 * v4.y;
            up.z += a2 * v4.z; up.w += a2 * v4.w;
        }
        *(float4*)(g_Yapart + (size_t)(chunk * BSc + b * Sc + w) * Dc + lane * 4) = up;
    }
}

// ---------------- stepC: 2 slot-rows per block --------------------------
// grid 64 blocks, 768 threads
__global__ void __launch_bounds__(768) stepC_kernel(int f, int emit, float* __restrict__ out_slots,
                             const float* __restrict__ bih, const float* __restrict__ bhh,
                             const float* __restrict__ g_ff, const float* __restrict__ be_ff,
                             const float* __restrict__ b1, const float* __restrict__ b2,
                             const float* __restrict__ g_sl, const float* __restrict__ be_sl) {
    __shared__ float yn[2][Dc], hs[2][Dc], hgs[2][Dc], ffs[2][Dc], hid[2][Dc], ln2[2][Dc];
    __shared__ float gp[2][2][384];   // [half][row][col] gi partials
    __shared__ float hp[2][2][384];   // [half][row][col] gh partials
    __shared__ float part[4][2][Dc];
    __shared__ float rsp[2][NCHUNK];
    __shared__ float red[2][4];

    const int t = threadIdx.x;
    const int bs0 = blockIdx.x * 2;

    if (t < 64) {
        int r = t >> 5, c = t & 31;
        rsp[r][c] = g_rspart[c * BSc + bs0 + r];
    }
    if (t < 256) {
        int r = t >> 7, d = t & 127;
        hs[r][d] = g_slots[(bs0 + r) * Dc + d];
    }
    __syncthreads();
    if (t < 256) {
        int r = t >> 7, d = t & 127;
        float ysum = 0.0f;
        #pragma unroll 8
        for (int c = 0; c < NCHUNK; c++) ysum += g_Yapart[(size_t)(c * BSc + bs0 + r) * Dc + d];
        float rsum = 0.0f;
        #pragma unroll
        for (int c = 0; c < NCHUNK; c++) rsum += rsp[r][c];
        yn[r][d] = ysum / rsum;
    }
    __syncthreads();

    // gate GEMVs, split-K 2: thread -> (half h, col j) for BOTH gi and gh
    {
        int h = (t >= 384) ? 1 : 0;
        int j = t - h * 384;
        int e0 = h * 64;
        float gi0 = 0.f, gi1 = 0.f, gh0 = 0.f, gh1 = 0.f;
        #pragma unroll 16
        for (int i = 0; i < 64; i++) {
            int e = e0 + i;
            float wc = g_WcT[e * 384 + j];
            float wh = g_WhhT[e * 384 + j];
            gi0 += wc * yn[0][e];
            gi1 += wc * yn[1][e];
            gh0 += wh * hs[0][e];
            gh1 += wh * hs[1][e];
        }
        gp[h][0][j] = gi0; gp[h][1][j] = gi1;
        hp[h][0][j] = gh0; hp[h][1][j] = gh1;
    }
    __syncthreads();

    float hg = 0.0f;
    if (t < 256) {
        int r = t >> 7, d = t & 127;
        float gi_r = gp[0][r][d]       + gp[1][r][d]       + g_bc[d]       + bih[d];
        float gh_r = hp[0][r][d]       + hp[1][r][d]       + bhh[d];
        float gi_z = gp[0][r][128 + d] + gp[1][r][128 + d] + g_bc[128 + d] + bih[128 + d];
        float gh_z = hp[0][r][128 + d] + hp[1][r][128 + d] + bhh[128 + d];
        float gi_n = gp[0][r][256 + d] + gp[1][r][256 + d] + g_bc[256 + d] + bih[256 + d];
        float gh_n = hp[0][r][256 + d] + hp[1][r][256 + d] + bhh[256 + d];
        float rr = sigmoidf_(gi_r + gh_r);
        float z  = sigmoidf_(gi_z + gh_z);
        float nn = tanhf(gi_n + rr * gh_n);
        hg = (1.0f - z) * nn + z * hs[r][d];
        hgs[r][d] = hg;
    }
    {
        float v = (t < 256) ? hg : 0.0f;
        float m = rowsum2(v, red) * (1.0f / 128.0f);
        float dx = (t < 256) ? (hg - m) : 0.0f;
        float var = rowsum2(dx * dx, red) * (1.0f / 128.0f);
        if (t < 256) {
            int r = t >> 7, d = t & 127;
            ffs[r][d] = dx * rsqrtf(var + 1e-5f) * g_ff[d] + be_ff[d];
        }
    }
    __syncthreads();

    if (t < 512) {
        int col = t & 127, h4 = t >> 7;
        float a0 = 0.f, a1 = 0.f;
        #pragma unroll 8
        for (int i = 0; i < 32; i++) {
            int d = h4 * 32 + i;
            float wv = g_W1T[d * Dc + col];
            a0 += wv * ffs[0][d];
            a1 += wv * ffs[1][d];
        }
        part[h4][0][col] = a0;
        part[h4][1][col] = a1;
    }
    __syncthreads();
    if (t < 256) {
        int r = t >> 7, d = t & 127;
        hid[r][d] = fmaxf(part[0][r][d] + part[1][r][d] + part[2][r][d] + part[3][r][d] + b1[d], 0.0f);
    }
    __syncthreads();

    if (t < 512) {
        int col = t & 127, h4 = t >> 7;
        float a0 = 0.f, a1 = 0.f;
        #pragma unroll 8
        for (int i = 0; i < 32; i++) {
            int d = h4 * 32 + i;
            float wv = g_W2T[d * Dc + col];
            a0 += wv * hid[0][d];
            a1 += wv * hid[1][d];
        }
        part[h4][0][col] = a0;
        part[h4][1][col] = a1;
    }
    __syncthreads();
    float snew = 0.0f;
    if (t < 256) {
        int r = t >> 7, d = t & 127;
        snew = hgs[r][d] + part[0][r][d] + part[1][r][d] + part[2][r][d] + part[3][r][d] + b2[d];
        g_slots[(bs0 + r) * Dc + d] = snew;
        if (emit) {
            int bs = bs0 + r;
            int b = bs >> 3, s = bs & 7;
            out_slots[(((size_t)b * NFc + f) * Sc + s) * Dc + d] = snew;
        }
    }

    {
        float v = (t < 256) ? snew : 0.0f;
        float m = rowsum2(v, red) * (1.0f / 128.0f);
        float dx = (t < 256) ? (snew - m) : 0.0f;
        float var = rowsum2(dx * dx, red) * (1.0f / 128.0f);
        if (t < 256) {
            int r = t >> 7, d = t & 127;
            ln2[r][d] = dx * rsqrtf(var + 1e-5f) * g_sl[d] + be_sl[d];
        }
    }
    __syncthreads();
    {
        float qv = 0.0f;
        if (t < 256) {
            int r = t >> 7, d = t & 127;
            qv = g_qbv[d] * ln2[r][d];
        }
        float qb = rowsum2(qv, red);
        if (t < 256 && (t & 127) == 0) g_qb[bs0 + (t >> 7)] = qb + g_qbb[0];
    }
    if (t < 512) {
        int col = t & 127, h4 = t >> 7;
        float a0 = 0.f, a1 = 0.f;
        #pragma unroll 8
        for (int i = 0; i < 32; i++) {
            int e = h4 * 32 + i;
            float wv = g_MT[e * 128 + col];
            a0 += wv * ln2[0][e];
            a1 += wv * ln2[1][e];
        }
        part[h4][0][col] = a0;
        part[h4][1][col] = a1;
    }
    __syncthreads();
    if (t < 256) {
        int r = t >> 7, d = t & 127;
        g_qt[(bs0 + r) * Dc + d] = part[0][r][d] + part[1][r][d] + part[2][r][d] + part[3][r][d] + g_qtb[d];
    }
}

// ---------------- launch ----------------
extern "C" void kernel_launch(void* const* d_in, const int* in_sizes, int n_in,
                              void* d_out, int out_size) {
    const float* inputs     = (const float*)d_in[0];
    const float* slots_init = (const float*)d_in[1];
    const float* Wq  = (const float*)d_in[2];
    const float* bq  = (const float*)d_in[3];
    const float* Wk  = (const float*)d_in[4];
    const float* bk  = (const float*)d_in[5];
    const float* Wv  = (const float*)d_in[6];
    const float* bv  = (const float*)d_in[7];
    const float* W1  = (const float*)d_in[8];
    const float* b1  = (const float*)d_in[9];
    const float* W2  = (const float*)d_in[10];
    const float* b2  = (const float*)d_in[11];
    const float* Wih = (const float*)d_in[12];
    const float* Whh = (const float*)d_in[13];
    const float* bih = (const float*)d_in[14];
    const float* bhh = (const float*)d_in[15];
    const float* g_in  = (const float*)d_in[16];
    const float* be_in = (const float*)d_in[17];
    const float* g_sl  = (const float*)d_in[18];
    const float* be_sl = (const float*)d_in[19];
    const float* g_ff  = (const float*)d_in[20];
    const float* be_ff = (const float*)d_in[21];

    float* out = (float*)d_out;
    float* out_slots = out;                                 // [B,NF,S,D]
    float* out_attn  = out + (size_t)Bc * NFc * Sc * Dc;    // [B,NF,S,N]

    prep_kernel<<<705, 256>>>(Wq, bq, Wk, bk, W1, W2, Wih, Whh, Wv, bv);
    init_kernel<<<BSc, 256>>>(slots_init, g_sl, be_sl);

    for (int step = 0; step < NFc + 1; step++) {
        int f = (step == 0) ? 0 : step - 1;
        int emit = (step > 0) ? 1 : 0;
        stepB_kernel<<<dim3(NCHUNK, Bc), 256>>>(inputs, f, emit, out_attn, g_in, be_in);
        stepC_kernel<<<64, 768>>>(f, emit, out_slots,
                                  bih, bhh, g_ff, be_ff, b1, b2, g_sl, be_sl);
    }
}